// round 5
// baseline (speedup 1.0000x reference)
#include <cuda_runtime.h>
#include <cuda_bf16.h>
#include <cstdint>

// ============================================================================
// HQQ grouped int4 GEMM, sm_103 base target, integer mma.sync path.
//
// W = q*s + zp (zp = z - 8s).  Per quant group g (K-chunk of 64):
//   x[m,k] ≈ srow[m,g] * (128*d1 + d2),  d1,d2 in s8 (exact 15-bit fixed pt)
//   P      = X @ q        via mma.m16n8k32.s32.s8.u8.s32 (EXACT s32)
//   mast  += float(P) * srow[m,g] * s[g,n]
//   out   += R @ Z^T      (rank-32 zero-point correction, bf16 hi/lo, 3 terms)
// ============================================================================

namespace {

constexpr int kE   = 8;
constexpr int kIN  = 2048;
constexpr int kOUT = 2048;
constexpr int kG   = 32;

constexpr int kBM  = 128;
constexpr int kBN  = 128;
constexpr int kBK  = 64;                  // == group size
constexpr int kNCh = kIN / kBK;           // 32
constexpr int kThreads = 512;             // 16 warps, 4x4 warp grid

// stage layout (byte offsets):
//   B  words [kw 0..15][n' 0..127]  (u8 q packed 4-k per word)   8 KB
//   Ahi words [kw][m']   (s8 high digit)                          8 KB
//   Alo words [kw][m']   (s8 low  digit)                          8 KB
//   scol float[128], srow float[128]
constexpr int kBOff    = 0;
constexpr int kAhiOff  = 8192;
constexpr int kAloOff  = 16384;
constexpr int kScolOff = 24576;
constexpr int kSrowOff = 25088;
constexpr int kStageB  = 25600;
constexpr int kRZoff   = 2 * kStageB;               // R_hi R_lo Z_hi Z_lo, 8KB each
constexpr int kSmemB   = kRZoff + 4 * 8192;         // 83968

constexpr float kSf = 16128.f;            // 126*128 fixed-point full scale

// ---------------------------------------------------------------------------

__device__ __forceinline__ uint32_t smem_u32(const void* p) {
  uint32_t a;
  asm("{ .reg .u64 t; cvta.to.shared.u64 t, %1; cvt.u32.u64 %0, t; }" : "=r"(a) : "l"(p));
  return a;
}

__device__ __forceinline__ uint32_t lds32(uint32_t a) {
  uint32_t r;
  asm volatile("ld.shared.b32 %0, [%1];" : "=r"(r) : "r"(a));
  return r;
}

__device__ __forceinline__ void ldsm_x4(uint32_t* r, uint32_t addr) {
  asm volatile("ldmatrix.sync.aligned.m8n8.x4.shared.b16 {%0,%1,%2,%3}, [%4];"
               : "=r"(r[0]), "=r"(r[1]), "=r"(r[2]), "=r"(r[3]) : "r"(addr));
}

__device__ __forceinline__ void ldsm_x2(uint32_t* r, uint32_t addr) {
  asm volatile("ldmatrix.sync.aligned.m8n8.x2.shared.b16 {%0,%1}, [%2];"
               : "=r"(r[0]), "=r"(r[1]) : "r"(addr));
}

__device__ __forceinline__ void mma_bf16(float* c, const uint32_t* a, const uint32_t* b) {
  asm volatile(
      "mma.sync.aligned.m16n8k16.row.col.f32.bf16.bf16.f32 "
      "{%0,%1,%2,%3}, {%4,%5,%6,%7}, {%8,%9}, {%0,%1,%2,%3};"
      : "+f"(c[0]), "+f"(c[1]), "+f"(c[2]), "+f"(c[3])
      : "r"(a[0]), "r"(a[1]), "r"(a[2]), "r"(a[3]), "r"(b[0]), "r"(b[1]));
}

__device__ __forceinline__ void mma_s8u8(int* c, const uint32_t* a,
                                         uint32_t b0, uint32_t b1) {
  asm volatile(
      "mma.sync.aligned.m16n8k32.row.col.s32.s8.u8.s32 "
      "{%0,%1,%2,%3}, {%4,%5,%6,%7}, {%8,%9}, {%0,%1,%2,%3};"
      : "+r"(c[0]), "+r"(c[1]), "+r"(c[2]), "+r"(c[3])
      : "r"(a[0]), "r"(a[1]), "r"(a[2]), "r"(a[3]), "r"(b0), "r"(b1));
}

// pack byte0 of four ints into one word: {a.b0, b.b0, c.b0, d.b0}
__device__ __forceinline__ uint32_t pack4b(int a, int b, int c, int d) {
  return __byte_perm(__byte_perm((uint32_t)a, (uint32_t)b, 0x0040),
                     __byte_perm((uint32_t)c, (uint32_t)d, 0x0040), 0x5410);
}

// ---------------------------------------------------------------------------

__global__ void __launch_bounds__(kThreads)
hqq_imma_kernel(const float* __restrict__ x,
                const int* __restrict__ qw,
                const float* __restrict__ snz,
                const int* __restrict__ tpe,
                float* __restrict__ out) {
  extern __shared__ __align__(1024) char smem[];
  const int tid = threadIdx.x;
  const int wid = tid >> 5;
  const int l   = tid & 31;

  const int e  = blockIdx.z;
  const int nt = blockIdx.x;
  const int mt = blockIdx.y;

  int off = 0, cnt = 0;
#pragma unroll
  for (int i = 0; i < kE; i++) {
    int c = __ldg(&tpe[i]);
    if (i < e) off += c;
    if (i == e) cnt = c;
  }
  if (mt * kBM >= cnt) return;

  const int row0  = off + mt * kBM;
  const int nrows = min(kBM, cnt - mt * kBM);
  const int n0    = nt * kBN;

  const uint32_t sbase = smem_u32(smem);

  // ---- warp-tile / fragment constants ----
  const int wm = wid >> 2;                 // 0..3 -> m base 32*wm
  const int wn = wid & 3;                  // 0..3 -> n base 32*wn
  const int l4  = l & 3;
  const int lq  = l >> 2;                  // 0..7
  const int mXor = l4 * 8;                 // word-index XOR for A/B swizzle
  // RZ correction fragment addressing (bf16 ldsm path, unchanged from R4)
  const int rowA0 = wm * 32 + (l & 15);
  const int segA  = l >> 4;
  const int rowB0 = wn * 32 + (l & 7);
  const int segB  = (l >> 3) & 1;

  // ---- staging ----
  float4 xv[2][2];
  int4   qv[4];
  float2 szv = make_float2(0.f, 0.f);

  float mast[32];
#pragma unroll
  for (int i = 0; i < 32; i++) mast[i] = 0.f;

  auto load_chunk = [&](int ch) {
    const int k0 = ch * kBK;
#pragma unroll
    for (int pm = 0; pm < 2; pm++) {
      const int m = 4 * wid + (l >> 3) + 64 * pm;
#pragma unroll
      for (int pc = 0; pc < 2; pc++) {
        xv[pm][pc] = (m < nrows)
            ? *(const float4*)(x + (size_t)(row0 + m) * kIN + k0 + ((l & 7) + 8 * pc) * 4)
            : make_float4(0.f, 0.f, 0.f, 0.f);
      }
    }
#pragma unroll
    for (int j = 0; j < 4; j++)
      qv[j] = *(const int4*)(qw + ((size_t)e * kIN + k0 + 4 * wid + j) * kOUT + n0 + 4 * l);
    if (tid < 128)
      szv = *(const float2*)(snz + (((size_t)e * kG + ch) * kOUT + n0 + tid) * 2);
  };

  auto store_chunk = [&](int buf, int ch) {
    char* st = smem + buf * kStageB;
    // ---- B: pack q (u8, exact) into k-quad words, layout [kw=wid][n'] ----
    {
      const int* qp = (const int*)qv;
      uint32_t w0 = pack4b(qp[0], qp[4], qp[8],  qp[12]);
      uint32_t w1 = pack4b(qp[1], qp[5], qp[9],  qp[13]);
      uint32_t w2 = pack4b(qp[2], qp[6], qp[10], qp[14]);
      uint32_t w3 = pack4b(qp[3], qp[7], qp[11], qp[15]);
      *(uint4*)(st + kBOff + wid * 512 + (((4 * l) ^ ((wid & 3) * 8)) * 4)) =
          make_uint4(w0, w1, w2, w3);
    }
    // ---- A: per-(row,group) fixed-point digits ----
#pragma unroll
    for (int pm = 0; pm < 2; pm++) {
      const int m = 4 * wid + (l >> 3) + 64 * pm;
      float mx = 1e-30f, rs = 0.f;
#pragma unroll
      for (int pc = 0; pc < 2; pc++) {
        const float4 v = xv[pm][pc];
        mx = fmaxf(mx, fmaxf(fmaxf(fabsf(v.x), fabsf(v.y)), fmaxf(fabsf(v.z), fabsf(v.w))));
        rs += (v.x + v.y) + (v.z + v.w);
      }
#pragma unroll
      for (int d = 1; d <= 4; d <<= 1) {
        mx = fmaxf(mx, __shfl_xor_sync(0xffffffffu, mx, d));
        rs += __shfl_xor_sync(0xffffffffu, rs, d);
      }
      const float srow = mx * (1.f / kSf);
      const float inv  = __fdividef(1.f, srow);
      if ((l & 7) == 0) {
        *(float*)(st + kSrowOff + m * 4) = srow;
        const __nv_bfloat16 rh = __float2bfloat16(rs);
        const __nv_bfloat16 rl = __float2bfloat16(rs - __bfloat162float(rh));
        *(__nv_bfloat16*)(smem + kRZoff        + m * 64 + ch * 2) = rh;
        *(__nv_bfloat16*)(smem + kRZoff + 8192 + m * 64 + ch * 2) = rl;
      }
#pragma unroll
      for (int pc = 0; pc < 2; pc++) {
        const float4 v = xv[pm][pc];
        const int X0 = __float2int_rn(v.x * inv);
        const int X1 = __float2int_rn(v.y * inv);
        const int X2 = __float2int_rn(v.z * inv);
        const int X3 = __float2int_rn(v.w * inv);
        const int h0 = (X0 + 64) >> 7, h1 = (X1 + 64) >> 7;
        const int h2 = (X2 + 64) >> 7, h3 = (X3 + 64) >> 7;
        const int g0 = X0 - (h0 << 7), g1 = X1 - (h1 << 7);
        const int g2 = X2 - (h2 << 7), g3 = X3 - (h3 << 7);
        const int cq = (l & 7) + 8 * pc;
        const uint32_t o = (uint32_t)(cq * 512 + ((m ^ ((cq & 3) * 8)) * 4));
        *(uint32_t*)(st + kAhiOff + o) = pack4b(h0, h1, h2, h3);
        *(uint32_t*)(st + kAloOff + o) = pack4b(g0, g1, g2, g3);
      }
    }
    // ---- scol + zero-point columns ----
    if (tid < 128) {
      const float s   = szv.x;
      const float zpf = szv.y - 8.f * s;
      *(float*)(st + kScolOff + tid * 4) = s;
      const __nv_bfloat16 zh = __float2bfloat16(zpf);
      const __nv_bfloat16 zl = __float2bfloat16(zpf - __bfloat162float(zh));
      *(__nv_bfloat16*)(smem + kRZoff + 16384 + tid * 64 + ch * 2) = zh;
      *(__nv_bfloat16*)(smem + kRZoff + 24576 + tid * 64 + ch * 2) = zl;
    }
  };

  // ---- main pipeline: single barrier per chunk, double-buffered ----
  load_chunk(0);
  for (int ch = 0; ch < kNCh; ch++) {
    const int buf = ch & 1;
    store_chunk(buf, ch);
    __syncthreads();
    if (ch + 1 < kNCh) load_chunk(ch + 1);

    const uint32_t Bb = sbase + buf * kStageB + kBOff;
    const uint32_t Ab = sbase + buf * kStageB + kAhiOff;

    int P[32];
#pragma unroll
    for (int i = 0; i < 32; i++) P[i] = 0;

#pragma unroll
    for (int dig = 0; dig < 2; dig++) {
      const uint32_t Ap = Ab + dig * 8192;
#pragma unroll
      for (int ks = 0; ks < 2; ks++) {
        const uint32_t rowoff = (uint32_t)((ks * 8 + l4) * 512);
        uint32_t Bf[4][2];
#pragma unroll
        for (int ni = 0; ni < 4; ni++) {
          const int n = wn * 32 + ni * 8 + lq;
          const uint32_t ba = Bb + rowoff + (uint32_t)((n ^ mXor) * 4);
          Bf[ni][0] = lds32(ba);
          Bf[ni][1] = lds32(ba + 4 * 512);
        }
#pragma unroll
        for (int mi = 0; mi < 2; mi++) {
          const int m0 = wm * 32 + mi * 16 + lq;
          const uint32_t e0 = (uint32_t)((m0 ^ mXor) * 4);
          const uint32_t e1 = (uint32_t)(((m0 + 8) ^ mXor) * 4);
          uint32_t A[4];
          A[0] = lds32(Ap + rowoff + e0);
          A[1] = lds32(Ap + rowoff + e1);
          A[2] = lds32(Ap + rowoff + 4 * 512 + e0);
          A[3] = lds32(Ap + rowoff + 4 * 512 + e1);
#pragma unroll
          for (int ni = 0; ni < 4; ni++)
            mma_s8u8(&P[(mi * 4 + ni) * 4], A, Bf[ni][0], Bf[ni][1]);
        }
      }
      if (dig == 0) {
#pragma unroll
        for (int i = 0; i < 32; i++) P[i] <<= 7;   // combine: P = 128*P_hi + P_lo
      }
    }

    // ---- rescale: mast += float(P) * srow * scol ----
    const uint32_t sc_b = sbase + buf * kStageB + kScolOff;
    float sr[2][2];
#pragma unroll
    for (int mi = 0; mi < 2; mi++) {
      const int m0 = wm * 32 + mi * 16 + lq;
      sr[mi][0] = *(const float*)(smem + buf * kStageB + kSrowOff + m0 * 4);
      sr[mi][1] = *(const float*)(smem + buf * kStageB + kSrowOff + (m0 + 8) * 4);
    }
#pragma unroll
    for (int ni = 0; ni < 4; ni++) {
      float2 sc;
      asm volatile("ld.shared.v2.f32 {%0,%1}, [%2];"
                   : "=f"(sc.x), "=f"(sc.y)
                   : "r"(sc_b + (uint32_t)((wn * 32 + ni * 8 + l4 * 2) * 4)));
#pragma unroll
      for (int mi = 0; mi < 2; mi++) {
        float* f = &mast[(mi * 4 + ni) * 4];
        const int* p = &P[(mi * 4 + ni) * 4];
        f[0] += (float)p[0] * (sr[mi][0] * sc.x);
        f[1] += (float)p[1] * (sr[mi][0] * sc.y);
        f[2] += (float)p[2] * (sr[mi][1] * sc.x);
        f[3] += (float)p[3] * (sr[mi][1] * sc.y);
      }
    }
    // no second barrier: store(buf) at ch+2 is ordered by the barrier at ch+1
  }

  // ---- rank-32 zero-point correction: mast += R @ Z^T (3-term bf16 hi/lo) ----
  {
    const uint32_t Rh = sbase + kRZoff;
    const uint32_t Rl = Rh + 8192;
    const uint32_t Zh = Rh + 16384;
    const uint32_t Zl = Rh + 24576;
#pragma unroll
    for (int ks = 0; ks < 2; ks++) {
      uint32_t Arh[2][4], Arl[2][4], Bzh[4][2], Bzl[4][2];
#pragma unroll
      for (int mi = 0; mi < 2; mi++) {
        const uint32_t o = (uint32_t)((rowA0 + mi * 16) * 64 + ks * 32 + segA * 16);
        ldsm_x4(Arh[mi], Rh + o);
        ldsm_x4(Arl[mi], Rl + o);
      }
#pragma unroll
      for (int ni = 0; ni < 4; ni++) {
        const uint32_t o = (uint32_t)((rowB0 + ni * 8) * 64 + ks * 32 + segB * 16);
        ldsm_x2(Bzh[ni], Zh + o);
        ldsm_x2(Bzl[ni], Zl + o);
      }
#pragma unroll
      for (int mi = 0; mi < 2; mi++)
#pragma unroll
        for (int ni = 0; ni < 4; ni++) {
          float* c = &mast[(mi * 4 + ni) * 4];
          mma_bf16(c, Arh[mi], Bzh[ni]);
          mma_bf16(c, Arl[mi], Bzh[ni]);
          mma_bf16(c, Arh[mi], Bzl[ni]);
        }
    }
  }

  // ---- epilogue ----
#pragma unroll
  for (int mi = 0; mi < 2; mi++) {
#pragma unroll
    for (int ni = 0; ni < 4; ni++) {
      const float* c = &mast[(mi * 4 + ni) * 4];
      const int r0  = wm * 32 + mi * 16 + lq;
      const int col = n0 + wn * 32 + ni * 8 + l4 * 2;
      if (r0 < nrows)
        *(float2*)(out + (size_t)(row0 + r0) * kOUT + col) = make_float2(c[0], c[1]);
      if (r0 + 8 < nrows)
        *(float2*)(out + (size_t)(row0 + r0 + 8) * kOUT + col) = make_float2(c[2], c[3]);
    }
  }
}

}  // namespace

// ---------------------------------------------------------------------------

extern "C" void kernel_launch(void* const* d_in, const int* in_sizes, int n_in,
                              void* d_out, int out_size) {
  (void)in_sizes; (void)n_in; (void)out_size;
  const float* x   = (const float*)d_in[0];
  const int*   qw  = (const int*)d_in[1];
  const float* snz = (const float*)d_in[2];
  const int*   tpe = (const int*)d_in[3];
  float* out = (float*)d_out;

  (void)cudaFuncSetAttribute(hqq_imma_kernel,
                             cudaFuncAttributeMaxDynamicSharedMemorySize, kSmemB);

  dim3 grid(kOUT / 128, 2048 / 128, kE);   // (16, 16, 8); empty m-tiles early-exit
  hqq_imma_kernel<<<grid, kThreads, kSmemB>>>(x, qw, snz, tpe, out);
}

// round 6
// speedup vs baseline: 2.3277x; 2.3277x over previous
#include <cuda_runtime.h>
#include <cuda_bf16.h>
#include <cuda_fp16.h>
#include <cstdint>

// ============================================================================
// HQQ grouped int4 GEMM, sm_103 base target, mma.sync fp16 path.
//
// W = q*s + zp (zp = z - 8s).  Per quant group g (K-chunk of 64):
//   P_g     = x_f16 @ q_f16     (q exact in fp16; x rounded, rel ~2^-11)
//   mast   += P_g * s[g, n]     (fp32 FFMA, s exact)
//   out    += R @ Z^T           (rank-32 zero-point correction, bf16 hi/lo)
// ============================================================================

namespace {

constexpr int kE   = 8;
constexpr int kIN  = 2048;
constexpr int kOUT = 2048;
constexpr int kG   = 32;

constexpr int kBM  = 128;
constexpr int kBN  = 128;
constexpr int kBK  = 64;                  // == group size
constexpr int kNCh = kIN / kBK;           // 32
constexpr int kThreads = 512;             // 16 warps, 4x4 warp grid

constexpr int kTileB  = kBM * kBK * 2;    // 16 KB fp16 tile
// stage: A | B | s[128] floats; stride padded to 1KB multiple
constexpr int kStageB = 2 * kTileB + 1024;           // 33792
constexpr int kRZoff  = 2 * kStageB;                 // R_hi R_lo Z_hi Z_lo, 8KB each
constexpr int kSmemB  = kRZoff + 4 * 8192;           // 100352

// ---------------------------------------------------------------------------

__device__ __forceinline__ uint32_t smem_u32(const void* p) {
  uint32_t a;
  asm("{ .reg .u64 t; cvta.to.shared.u64 t, %1; cvt.u32.u64 %0, t; }" : "=r"(a) : "l"(p));
  return a;
}

__device__ __forceinline__ uint32_t pack_f16x2(float lo, float hi) {
  uint32_t r;
  asm("cvt.rn.f16x2.f32 %0, %1, %2;" : "=r"(r) : "f"(hi), "f"(lo));
  return r;
}

__device__ __forceinline__ uint32_t sw128(uint32_t off) {
  return off ^ ((off >> 3) & 0x70);
}

__device__ __forceinline__ void ldsm_x4(uint32_t* r, uint32_t addr) {
  asm volatile("ldmatrix.sync.aligned.m8n8.x4.shared.b16 {%0,%1,%2,%3}, [%4];"
               : "=r"(r[0]), "=r"(r[1]), "=r"(r[2]), "=r"(r[3]) : "r"(addr));
}

__device__ __forceinline__ void ldsm_x2(uint32_t* r, uint32_t addr) {
  asm volatile("ldmatrix.sync.aligned.m8n8.x2.shared.b16 {%0,%1}, [%2];"
               : "=r"(r[0]), "=r"(r[1]) : "r"(addr));
}

__device__ __forceinline__ void mma_f16(float* c, const uint32_t* a,
                                        uint32_t b0, uint32_t b1) {
  asm volatile(
      "mma.sync.aligned.m16n8k16.row.col.f32.f16.f16.f32 "
      "{%0,%1,%2,%3}, {%4,%5,%6,%7}, {%8,%9}, {%0,%1,%2,%3};"
      : "+f"(c[0]), "+f"(c[1]), "+f"(c[2]), "+f"(c[3])
      : "r"(a[0]), "r"(a[1]), "r"(a[2]), "r"(a[3]), "r"(b0), "r"(b1));
}

__device__ __forceinline__ void mma_bf16(float* c, const uint32_t* a, const uint32_t* b) {
  asm volatile(
      "mma.sync.aligned.m16n8k16.row.col.f32.bf16.bf16.f32 "
      "{%0,%1,%2,%3}, {%4,%5,%6,%7}, {%8,%9}, {%0,%1,%2,%3};"
      : "+f"(c[0]), "+f"(c[1]), "+f"(c[2]), "+f"(c[3])
      : "r"(a[0]), "r"(a[1]), "r"(a[2]), "r"(a[3]), "r"(b[0]), "r"(b[1]));
}

// ---------------------------------------------------------------------------

__global__ void __launch_bounds__(kThreads)
hqq_mma_kernel(const float* __restrict__ x,
               const int* __restrict__ qw,
               const float* __restrict__ snz,
               const int* __restrict__ tpe,
               float* __restrict__ out) {
  extern __shared__ __align__(1024) char smem[];
  const int tid = threadIdx.x;
  const int wid = tid >> 5;
  const int l   = tid & 31;

  const int e  = blockIdx.z;
  const int nt = blockIdx.x;
  const int mt = blockIdx.y;

  int off = 0, cnt = 0;
#pragma unroll
  for (int i = 0; i < kE; i++) {
    int c = __ldg(&tpe[i]);
    if (i < e) off += c;
    if (i == e) cnt = c;
  }
  if (mt * kBM >= cnt) return;

  const int row0  = off + mt * kBM;
  const int nrows = min(kBM, cnt - mt * kBM);
  const int n0    = nt * kBN;

  const uint32_t sbase = smem_u32(smem);

  // ---- fill mappings (identical to the passing R4 kernel) ----
  const int a_c4 = l & 15;
  const int a_mr = tid >> 4;
  const int b_n0  = 2 * ((wid & 7) * 8 + (l >> 2));
  const int b_kpb = (wid >> 3) * 16 + (l & 3);

  // ---- mma fragment addressing ----
  const int wm = wid >> 2;
  const int wn = wid & 3;
  const int rowA0 = wm * 32 + (l & 15);
  const int segA  = l >> 4;
  // B via ldsm_x4 over ni pairs: lanes 0-15 -> ni, 16-31 -> ni+1
  const int rowBx4 = wn * 32 + ((l >> 4) & 1) * 8 + (l & 7);
  const int segBx4 = (l >> 3) & 1;
  // rank-32 correction uses the x2 form
  const int rowB0 = wn * 32 + (l & 7);
  const int segB  = (l >> 3) & 1;

  // ---- staging ----
  float4 xv[4];
  int2   qva[4], qvb[4];
  float2 szv = make_float2(0.f, 0.f);

  float mast[32];
#pragma unroll
  for (int i = 0; i < 32; i++) mast[i] = 0.f;

  auto load_chunk = [&](int ch) {
    const int k0 = ch * kBK;
    const float* xp = x + ((size_t)(row0 + a_mr)) * kIN + k0 + a_c4 * 4;
#pragma unroll
    for (int p = 0; p < 4; p++) {
      const int m = a_mr + p * 32;
      xv[p] = (m < nrows) ? *(const float4*)(xp + (size_t)p * 32 * kIN)
                          : make_float4(0.f, 0.f, 0.f, 0.f);
    }
    const int* qb = qw + ((size_t)e * kIN + k0) * kOUT + n0 + b_n0;
#pragma unroll
    for (int p = 0; p < 4; p++) {
      const int kk = 2 * (b_kpb + 4 * p);
      qva[p] = *(const int2*)(qb + (size_t)kk * kOUT);
      qvb[p] = *(const int2*)(qb + (size_t)(kk + 1) * kOUT);
    }
    if (tid < 128)
      szv = *(const float2*)(snz + (((size_t)e * kG + ch) * kOUT + n0 + tid) * 2);
  };

  auto store_chunk = [&](int buf, int ch) {
    char* st = smem + buf * kStageB;
    // A tile: fp32 -> fp16, SW128; one float4 -> 8 bytes at col c4*8
#pragma unroll
    for (int p = 0; p < 4; p++) {
      const int m = a_mr + p * 32;
      const float4 v = xv[p];
      const uint32_t h0 = pack_f16x2(v.x, v.y);
      const uint32_t h1 = pack_f16x2(v.z, v.w);
      const uint32_t o = sw128((uint32_t)(m * 128 + a_c4 * 8));
      *(uint2*)(st + o) = make_uint2(h0, h1);
      // rowsum over this group's 64 cols (16-lane half-warp reduction)
      float rs = (v.x + v.y) + (v.z + v.w);
      rs += __shfl_xor_sync(0xffffffffu, rs, 1);
      rs += __shfl_xor_sync(0xffffffffu, rs, 2);
      rs += __shfl_xor_sync(0xffffffffu, rs, 4);
      rs += __shfl_xor_sync(0xffffffffu, rs, 8);
      if ((l & 15) == 0) {
        const __nv_bfloat16 rh = __float2bfloat16(rs);
        const __nv_bfloat16 rl = __float2bfloat16(rs - __bfloat162float(rh));
        *(__nv_bfloat16*)(smem + kRZoff        + m * 64 + ch * 2) = rh;
        *(__nv_bfloat16*)(smem + kRZoff + 8192 + m * 64 + ch * 2) = rl;
      }
    }
    // B tile: q -> fp16 (exact), N-major rows (128B), SW128
#pragma unroll
    for (int p = 0; p < 4; p++) {
      const int kp = b_kpb + 4 * p;
      const uint32_t h_r0 = pack_f16x2((float)qva[p].x, (float)qvb[p].x);
      const uint32_t h_r1 = pack_f16x2((float)qva[p].y, (float)qvb[p].y);
      *(uint32_t*)(st + kTileB + sw128((uint32_t)(b_n0 * 128 + kp * 4)))       = h_r0;
      *(uint32_t*)(st + kTileB + sw128((uint32_t)((b_n0 + 1) * 128 + kp * 4))) = h_r1;
    }
    // s array + Z (zp) hi/lo columns for this group
    if (tid < 128) {
      const float s   = szv.x;
      const float zpf = szv.y - 8.f * s;
      *(float*)(st + 2 * kTileB + tid * 4) = s;
      const __nv_bfloat16 zh = __float2bfloat16(zpf);
      const __nv_bfloat16 zl = __float2bfloat16(zpf - __bfloat162float(zh));
      *(__nv_bfloat16*)(smem + kRZoff + 16384 + tid * 64 + ch * 2) = zh;
      *(__nv_bfloat16*)(smem + kRZoff + 24576 + tid * 64 + ch * 2) = zl;
    }
  };

  // ---- main pipeline: single barrier per chunk, double-buffered ----
  load_chunk(0);
  for (int ch = 0; ch < kNCh; ch++) {
    const int buf = ch & 1;
    store_chunk(buf, ch);
    __syncthreads();
    if (ch + 1 < kNCh) load_chunk(ch + 1);

    float P[32];
#pragma unroll
    for (int i = 0; i < 32; i++) P[i] = 0.f;

    const uint32_t base = sbase + buf * kStageB;
#pragma unroll
    for (int ks = 0; ks < 4; ks++) {
      uint32_t Af[2][4], Bf[4][2];
#pragma unroll
      for (int mi = 0; mi < 2; mi++) {
        const int row = rowA0 + mi * 16;
        const uint32_t o = (uint32_t)(row * 128) +
                           (((uint32_t)(ks * 32 + segA * 16)) ^ ((row & 7) << 4));
        ldsm_x4(Af[mi], base + o);
      }
#pragma unroll
      for (int np = 0; np < 2; np++) {     // ni pairs {0,1} and {2,3}
        const int row = rowBx4 + np * 16;
        const uint32_t o = (uint32_t)(row * 128) +
                           (((uint32_t)(ks * 32 + segBx4 * 16)) ^ ((row & 7) << 4));
        uint32_t r[4];
        ldsm_x4(r, base + kTileB + o);
        Bf[np * 2][0]     = r[0];
        Bf[np * 2][1]     = r[1];
        Bf[np * 2 + 1][0] = r[2];
        Bf[np * 2 + 1][1] = r[3];
      }
#pragma unroll
      for (int mi = 0; mi < 2; mi++)
#pragma unroll
        for (int ni = 0; ni < 4; ni++)
          mma_f16(&P[(mi * 4 + ni) * 4], Af[mi], Bf[ni][0], Bf[ni][1]);
    }

    // rescale: mast += P * s[n]
    const uint32_t sb = base + 2 * kTileB;
#pragma unroll
    for (int ni = 0; ni < 4; ni++) {
      float2 sv;
      asm volatile("ld.shared.v2.f32 {%0,%1}, [%2];"
                   : "=f"(sv.x), "=f"(sv.y)
                   : "r"(sb + (uint32_t)((wn * 32 + ni * 8 + (l & 3) * 2) * 4)));
#pragma unroll
      for (int mi = 0; mi < 2; mi++) {
        float* f = &mast[(mi * 4 + ni) * 4];
        const float* p = &P[(mi * 4 + ni) * 4];
        f[0] += p[0] * sv.x;
        f[1] += p[1] * sv.y;
        f[2] += p[2] * sv.x;
        f[3] += p[3] * sv.y;
      }
    }
    // no second barrier: store(buf) at ch+2 is ordered by the barrier at ch+1
  }

  // ---- rank-32 zero-point correction: mast += R @ Z^T (3-term bf16 hi/lo) ----
  {
    const uint32_t Rh = sbase + kRZoff;
    const uint32_t Rl = Rh + 8192;
    const uint32_t Zh = Rh + 16384;
    const uint32_t Zl = Rh + 24576;
#pragma unroll
    for (int ks = 0; ks < 2; ks++) {
      uint32_t Arh[2][4], Arl[2][4], Bzh[4][2], Bzl[4][2];
#pragma unroll
      for (int mi = 0; mi < 2; mi++) {
        const uint32_t o = (uint32_t)((rowA0 + mi * 16) * 64 + ks * 32 + segA * 16);
        ldsm_x4(Arh[mi], Rh + o);
        ldsm_x4(Arl[mi], Rl + o);
      }
#pragma unroll
      for (int ni = 0; ni < 4; ni++) {
        const uint32_t o = (uint32_t)((rowB0 + ni * 8) * 64 + ks * 32 + segB * 16);
        ldsm_x2(Bzh[ni], Zh + o);
        ldsm_x2(Bzl[ni], Zl + o);
      }
#pragma unroll
      for (int mi = 0; mi < 2; mi++)
#pragma unroll
        for (int ni = 0; ni < 4; ni++) {
          float* c = &mast[(mi * 4 + ni) * 4];
          mma_bf16(c, Arh[mi], Bzh[ni]);
          mma_bf16(c, Arl[mi], Bzh[ni]);
          mma_bf16(c, Arh[mi], Bzl[ni]);
        }
    }
  }

  // ---- epilogue ----
#pragma unroll
  for (int mi = 0; mi < 2; mi++) {
#pragma unroll
    for (int ni = 0; ni < 4; ni++) {
      const float* c = &mast[(mi * 4 + ni) * 4];
      const int r0  = wm * 32 + mi * 16 + (l >> 2);
      const int col = n0 + wn * 32 + ni * 8 + (l & 3) * 2;
      if (r0 < nrows)
        *(float2*)(out + (size_t)(row0 + r0) * kOUT + col) = make_float2(c[0], c[1]);
      if (r0 + 8 < nrows)
        *(float2*)(out + (size_t)(row0 + r0 + 8) * kOUT + col) = make_float2(c[2], c[3]);
    }
  }
}

}  // namespace

// ---------------------------------------------------------------------------

extern "C" void kernel_launch(void* const* d_in, const int* in_sizes, int n_in,
                              void* d_out, int out_size) {
  (void)in_sizes; (void)n_in; (void)out_size;
  const float* x   = (const float*)d_in[0];
  const int*   qw  = (const int*)d_in[1];
  const float* snz = (const float*)d_in[2];
  const int*   tpe = (const int*)d_in[3];
  float* out = (float*)d_out;

  (void)cudaFuncSetAttribute(hqq_mma_kernel,
                             cudaFuncAttributeMaxDynamicSharedMemorySize, kSmemB);

  dim3 grid(kOUT / kBN, 2048 / kBM, kE);   // (16, 16, 8); empty m-tiles early-exit
  hqq_mma_kernel<<<grid, kThreads, kSmemB>>>(x, qw, snz, tpe, out);
}